// round 15
// baseline (speedup 1.0000x reference)
#include <cuda_runtime.h>
#include <cuda_fp16.h>
#include <cstdint>

#define B_  32
#define T_  512
#define H_  1024
#define G4_ 4096
#define M_  (B_ * T_)   // 16384
#define NBLK 128
#define NTHR 512
#define CSTR 64          // counter stride in u32 (256 B)
#define NC0  8           // f0 counters: stripe = bid>>4 (16 blocks each)
#define NC1  16          // f1 counters: stripe = bid&15 (8 blocks each)

// ---------------- static device scratch ----------------
__device__ float g_xg[(size_t)M_ * G4_];     // layer-0 gate preactivations (from GEMM0)
__device__ unsigned g_h0H[4][16384];         // frag-permuted fp16 h0, depth-4 (slot r&3)
__device__ unsigned g_h1H[2][16384];         // h1, parity
__device__ unsigned g_f0[NC0 * CSTR];        // h0-publish flags (per-warp release: +8/block/round)
__device__ unsigned g_f1[NC1 * CSTR];        // L1-done flags   (per-warp release: +8/block/round)

// ---------------- helpers ----------------
__device__ __forceinline__ void mma_f16(float& c0, float& c1, float& c2, float& c3,
                                        uint32_t a0, uint32_t a1, uint32_t a2, uint32_t a3,
                                        uint32_t b0, uint32_t b1) {
    asm volatile(
        "mma.sync.aligned.m16n8k16.row.col.f32.f16.f16.f32 "
        "{%0,%1,%2,%3},{%4,%5,%6,%7},{%8,%9},{%0,%1,%2,%3};"
        : "+f"(c0), "+f"(c1), "+f"(c2), "+f"(c3)
        : "r"(a0), "r"(a1), "r"(a2), "r"(a3), "r"(b0), "r"(b1));
}

__device__ __forceinline__ float tanha(float x) {
    float y;
    asm("tanh.approx.f32 %0, %1;" : "=f"(y) : "f"(x));
    return y;
}
__device__ __forceinline__ float sigm(float x) {
    return fmaf(tanha(0.5f * x), 0.5f, 0.5f);
}

__device__ __forceinline__ unsigned pack_h2(float a, float b) {
    __half2 h = __floats2half2_rn(a, b);
    return *(unsigned*)&h;
}

__device__ __forceinline__ void barn(int id, int cnt) {
    asm volatile("bar.sync %0, %1;" :: "r"(id), "r"(cnt) : "memory");
}

__device__ __forceinline__ void flag_release_idx(unsigned* base, int idx) {
    asm volatile("red.release.gpu.global.add.u32 [%0], 1;"
                 :: "l"(&base[idx * CSTR]) : "memory");
}

__device__ __forceinline__ void flag_poll(const unsigned* base, int idx, unsigned target) {
    const unsigned* cp = &base[idx * CSTR];
    unsigned v;
    asm volatile("ld.acquire.gpu.global.u32 %0, [%1];" : "=r"(v) : "l"(cp) : "memory");
    while (v < target) {
        __nanosleep(64);
        asm volatile("ld.acquire.gpu.global.u32 %0, [%1];" : "=r"(v) : "l"(cp) : "memory");
    }
}

// ---------------- big GEMM (fp16 mma): C[M,4096] = A[M,1024]*W^T + bias ----------------
#define GS_ 12

__global__ __launch_bounds__(256, 2)
void gemm_xg_kernel(const float* __restrict__ A,
                    const float* __restrict__ W,
                    const float* __restrict__ b0,
                    const float* __restrict__ b1,
                    float* __restrict__ C)
{
    __shared__ unsigned Ash[128 * GS_];
    __shared__ unsigned Bsh[128 * GS_];

    const int tid  = threadIdx.x;
    const int wid  = tid >> 5, lane = tid & 31;
    const int g    = lane >> 2, t = lane & 3;
    const int wm   = wid & 1, wn = wid >> 1;
    const int cm   = blockIdx.y * 128;
    const int cn   = blockIdx.x * 128;

    float acc[4][4][4];
    #pragma unroll
    for (int i = 0; i < 4; i++)
        #pragma unroll
        for (int j = 0; j < 4; j++)
            #pragma unroll
            for (int q = 0; q < 4; q++) acc[i][j][q] = 0.0f;

    const int r0 = tid >> 1;
    const int q0 = tid & 1;

    const float* Ag = A + (size_t)(cm + r0) * 1024 + 8 * q0;
    const float* Bg = W + (size_t)(cn + r0) * 1024 + 8 * q0;

    float4 av0 = *(const float4*)(Ag);
    float4 av1 = *(const float4*)(Ag + 4);
    float4 bv0 = *(const float4*)(Bg);
    float4 bv1 = *(const float4*)(Bg + 4);

    for (int kk = 0; kk < 1024; kk += 16) {
        __syncthreads();
        {
            uint4 pa, pb;
            pa.x = pack_h2(av0.x, av0.y); pa.y = pack_h2(av0.z, av0.w);
            pa.z = pack_h2(av1.x, av1.y); pa.w = pack_h2(av1.z, av1.w);
            pb.x = pack_h2(bv0.x, bv0.y); pb.y = pack_h2(bv0.z, bv0.w);
            pb.z = pack_h2(bv1.x, bv1.y); pb.w = pack_h2(bv1.z, bv1.w);
            *(uint4*)(Ash + r0 * GS_ + 4 * q0) = pa;
            *(uint4*)(Bsh + r0 * GS_ + 4 * q0) = pb;
        }
        __syncthreads();

        if (kk + 16 < 1024) {
            av0 = *(const float4*)(Ag + kk + 16);
            av1 = *(const float4*)(Ag + kk + 20);
            bv0 = *(const float4*)(Bg + kk + 16);
            bv1 = *(const float4*)(Bg + kk + 20);
        }

        uint32_t af[4][4];
        uint32_t bf[4][2];
        #pragma unroll
        for (int mt = 0; mt < 4; mt++) {
            int rb = wm * 64 + mt * 16;
            af[mt][0] = Ash[(rb + g)     * GS_ + t];
            af[mt][1] = Ash[(rb + g + 8) * GS_ + t];
            af[mt][2] = Ash[(rb + g)     * GS_ + t + 4];
            af[mt][3] = Ash[(rb + g + 8) * GS_ + t + 4];
        }
        #pragma unroll
        for (int nt = 0; nt < 4; nt++) {
            int nb = wn * 32 + nt * 8 + g;
            bf[nt][0] = Bsh[nb * GS_ + t];
            bf[nt][1] = Bsh[nb * GS_ + t + 4];
        }
        #pragma unroll
        for (int mt = 0; mt < 4; mt++)
            #pragma unroll
            for (int nt = 0; nt < 4; nt++)
                mma_f16(acc[mt][nt][0], acc[mt][nt][1], acc[mt][nt][2], acc[mt][nt][3],
                        af[mt][0], af[mt][1], af[mt][2], af[mt][3],
                        bf[nt][0], bf[nt][1]);
    }

    #pragma unroll
    for (int mt = 0; mt < 4; mt++) {
        #pragma unroll
        for (int nt = 0; nt < 4; nt++) {
            int m = cm + wm * 64 + mt * 16 + g;
            int n = cn + wn * 32 + nt * 8 + 2 * t;
            float bs0 = b0[n] + b1[n];
            float bs1 = b0[n + 1] + b1[n + 1];
            float2 v0 = make_float2(acc[mt][nt][0] + bs0, acc[mt][nt][1] + bs1);
            float2 v1 = make_float2(acc[mt][nt][2] + bs0, acc[mt][nt][3] + bs1);
            *(float2*)(C + (size_t)m * G4_ + n) = v0;
            *(float2*)(C + (size_t)(m + 8) * G4_ + n) = v1;
        }
    }
}

// ---------------- fused two-layer scan, per-warp producer-aligned dataflow ----------------
// Warps 8-15 = layer-0 (critical path); warps 0-7 = layer-1.
// L1 loads batched in 2 half-batches of 16 LDG.128 (deep MLP vs L2 latency).
#define WA_  16384
#define WB_  32768
#define RPK  17
#define RPKS (8 * 32 * RPK)
#define FUSED_SMEM ((WA_ + WB_ + 2 * RPKS) * 4)   // 231424 B (hbuf lives in RPK holes)

__global__ __launch_bounds__(NTHR, 1)
void lstm_fused_kernel(const float* __restrict__ xg,
                       const float* __restrict__ Whh0,
                       const float* __restrict__ Wih1,
                       const float* __restrict__ Whh1,
                       const float* __restrict__ bih1,
                       const float* __restrict__ bhh1,
                       float* __restrict__ outseq)
{
    extern __shared__ unsigned smu[];
    unsigned* WshA = smu;
    unsigned* WshB = smu + WA_;
    unsigned* RshA = smu + WA_ + WB_;
    unsigned* RshB = RshA + RPKS;

    const int tid  = threadIdx.x;
    const int bid  = blockIdx.x;
    const int wid  = tid >> 5, lane = tid & 31;
    const int g    = lane >> 2, t = lane & 3;

    // ---- fill Whh0 frags ----
    for (int e = tid; e < WA_; e += NTHR) {
        int rr = e & 1;
        int ln = (e >> 1) & 31;
        int nt = (e >> 6) & 3;
        int si = (e >> 8) & 7;
        int kq = e >> 11;
        int n8 = ln >> 2, tt = ln & 3;
        int row = nt * 1024 + bid * 8 + n8;
        int k0  = kq * 128 + si * 16 + 2 * tt + rr * 8;
        WshA[e] = pack_h2(Whh0[(size_t)row * 1024 + k0],
                          Whh0[(size_t)row * 1024 + k0 + 1]);
    }
    // ---- fill [Wih1|Whh1] frags (K=2048) ----
    for (int e = tid; e < WB_; e += NTHR) {
        int rr = e & 1;
        int ln = (e >> 1) & 31;
        int nt = (e >> 6) & 3;
        int si = (e >> 8) & 15;
        int kq = e >> 12;
        int n8 = ln >> 2, tt = ln & 3;
        int row = nt * 1024 + bid * 8 + n8;
        int kg  = kq * 256 + si * 16 + 2 * tt + rr * 8;
        const float* src = (kg < 1024) ? (Wih1 + (size_t)row * 1024 + kg)
                                       : (Whh1 + (size_t)row * 1024 + (kg - 1024));
        WshB[e] = pack_h2(src[0], src[1]);
    }

    const int cix  = tid & 255;
    const int eb   = cix >> 3;
    const int ej   = cix & 7;
    const int hcol = bid * 8 + ej;
    const int c_   = bid >> 1;
    const int fmt  = eb >> 4;
    const int ridx = (bid & 1) * 2 + ((eb >> 3) & 1);
    const int foff = (((c_ * 2 + fmt) * 32) + (eb & 7) * 4 + (ej >> 1)) * 4 + ridx;

    // hbuf slot d (0..3) lives in the RPK padding holes (col 16)
    const int hb_row = (cix >> 1) * RPK + 16;
    const int hb_sel = cix & 1;

    float c0_state = 0.0f, c1_state = 0.0f;
    float bias1[4];
    if (tid >= 256) {                           // L0 half
        if ((ej & 1) == 0) g_h0H[3][foff] = 0u; // h0[-1] -> slot 3
    } else {                                    // L1 half
        #pragma unroll
        for (int q = 0; q < 4; q++)
            bias1[q] = bih1[q * 1024 + hcol] + bhh1[q * 1024 + hcol];
        if ((ej & 1) == 0) g_h1H[1][foff] = 0u; // h1[-1] -> parity 1
    }

    // init publish: every L0 warp releases once
    __syncthreads();
    if (tid >= 256 && lane == 0) flag_release_idx(g_f0, bid >> 4);

    if (tid >= 256) {
        // ================= layer-0 chain (warps 8-15) =================
        const int kq = wid - 8;
        for (int r = 0; r < T_; r++) {
            // prefetch xg (independent of flags)
            const float* xp = xg + ((size_t)eb * T_ + r) * G4_ + hcol;
            float xv0 = __ldcs(xp);
            float xv1 = __ldcs(xp + 1024);
            float xv2 = __ldcs(xp + 2048);
            float xv3 = __ldcs(xp + 3072);

            // merged waits: lane0 -> my 16 producers' h0[r-1]; lanes 16.. -> L1 antidep (lag<=2)
            if (lane == 0) flag_poll(g_f0, kq, (unsigned)(r + 1) * 128u);
            else if (lane >= 16 && r >= 3)
                flag_poll(g_f1, lane - 16, (unsigned)(r - 2) * 64u);
            __syncwarp();

            float acc[2][4][4];
            #pragma unroll
            for (int mt = 0; mt < 2; mt++)
                #pragma unroll
                for (int nt = 0; nt < 4; nt++)
                    #pragma unroll
                    for (int q = 0; q < 4; q++) acc[mt][nt][q] = 0.0f;

            const uint4* hA = (const uint4*)g_h0H[(r + 3) & 3];   // h0[r-1]
            uint4 a[2][4][2];
            #pragma unroll
            for (int h2 = 0; h2 < 2; h2++)
                #pragma unroll
                for (int s = 0; s < 4; s++) {
                    int c = kq * 8 + h2 * 4 + s;
                    a[h2][s][0] = __ldcg(hA + (c * 2 + 0) * 32 + lane);
                    a[h2][s][1] = __ldcg(hA + (c * 2 + 1) * 32 + lane);
                }
            #pragma unroll
            for (int h2 = 0; h2 < 2; h2++)
                #pragma unroll
                for (int s = 0; s < 4; s++) {
                    int si = h2 * 4 + s;
                    #pragma unroll
                    for (int nt = 0; nt < 4; nt++) {
                        uint2 w = *(const uint2*)(WshA + (((kq * 8 + si) * 4 + nt) << 6) + lane * 2);
                        mma_f16(acc[0][nt][0], acc[0][nt][1], acc[0][nt][2], acc[0][nt][3],
                                a[h2][s][0].x, a[h2][s][0].y, a[h2][s][0].z, a[h2][s][0].w, w.x, w.y);
                        mma_f16(acc[1][nt][0], acc[1][nt][1], acc[1][nt][2], acc[1][nt][3],
                                a[h2][s][1].x, a[h2][s][1].y, a[h2][s][1].z, a[h2][s][1].w, w.x, w.y);
                    }
                }

            barn(2, 256);                      // RshA free (prev round's reduce done)
            #pragma unroll
            for (int mt = 0; mt < 2; mt++)
                #pragma unroll
                for (int nt = 0; nt < 4; nt++) {
                    int row = kq * 32 + mt * 16 + g;
                    RshA[row * RPK + nt * 4 + t]       = pack_h2(acc[mt][nt][0], acc[mt][nt][1]);
                    RshA[(row + 8) * RPK + nt * 4 + t] = pack_h2(acc[mt][nt][2], acc[mt][nt][3]);
                }
            barn(1, 256);                      // partials ready

            float s0 = xv0, s1 = xv1, s2 = xv2, s3 = xv3;
            const int sel = ej & 1;
            #pragma unroll
            for (int kk = 0; kk < 8; kk++) {
                const unsigned* rp = RshA + (kk * 32 + eb) * RPK + (ej >> 1);
                #pragma unroll
                for (int q = 0; q < 4; q++) {
                    __half2 hv = *(const __half2*)&rp[q * 4];
                    float2 f = __half22float2(hv);
                    float v = sel ? f.y : f.x;
                    if (q == 0) s0 += v; else if (q == 1) s1 += v;
                    else if (q == 2) s2 += v; else s3 += v;
                }
            }
            float iv = sigm(s0), fv = sigm(s1), gv = tanha(s2), ov = sigm(s3);
            c0_state = fv * c0_state + iv * gv;
            float hval = ov * tanha(c0_state);

            // publish h0[r] (frag-permuted fp16) + residual into hbuf hole
            unsigned hb = (unsigned)__half_as_ushort(__float2half_rn(hval));
            unsigned ob = __shfl_xor_sync(0xffffffffu, hb, 1);
            int d = r & 3;
            if ((ej & 1) == 0)
                g_h0H[d][foff] = (hb & 0xffffu) | (ob << 16);
            {
                unsigned* hrow = (d < 2 ? RshA : RshB) + (d & 1) * 128 * RPK + hb_row;
                ((__half*)hrow)[hb_sel] = __float2half_rn(hval);
            }
            __syncwarp();
            if (lane == 0) flag_release_idx(g_f0, bid >> 4);
        }
    } else {
        // ================= layer-1 chain (warps 0-7) =================
        const int kq = wid;
        for (int r = 1; r <= T_; r++) {
            // per-warp waits
            if (kq < 4) {
                if (lane < 2) flag_poll(g_f0, 2 * kq + lane, (unsigned)(r + 1) * 128u);
            } else {
                if (r == 1) { if (lane < NC0) flag_poll(g_f0, lane, 2u * 128u); }
                else        { if (lane < NC1) flag_poll(g_f1, lane, (unsigned)(r - 1) * 64u); }
            }
            __syncwarp();

            float acc[2][4][4];
            #pragma unroll
            for (int mt = 0; mt < 2; mt++)
                #pragma unroll
                for (int nt = 0; nt < 4; nt++)
                    #pragma unroll
                    for (int q = 0; q < 4; q++) acc[mt][nt][q] = 0.0f;

            const uint4* baseA;
            int cb;
            if (kq < 4) { baseA = (const uint4*)g_h0H[(r + 3) & 3]; cb = kq * 16; }       // h0[r-1]
            else        { baseA = (const uint4*)g_h1H[r & 1];       cb = (kq - 4) * 16; } // h1[r-1 of L1 chain]

            // two fully-batched half-batches: 16 LDG.128 in flight each
            #pragma unroll
            for (int half = 0; half < 2; half++) {
                uint4 b[8][2];
                #pragma unroll
                for (int s = 0; s < 8; s++) {
                    int c = cb + half * 8 + s;
                    b[s][0] = __ldcg(baseA + (c * 2 + 0) * 32 + lane);
                    b[s][1] = __ldcg(baseA + (c * 2 + 1) * 32 + lane);
                }
                #pragma unroll
                for (int s = 0; s < 8; s++) {
                    int si = half * 8 + s;
                    #pragma unroll
                    for (int nt = 0; nt < 4; nt++) {
                        uint2 w = *(const uint2*)(WshB + (((kq * 16 + si) * 4 + nt) << 6) + lane * 2);
                        mma_f16(acc[0][nt][0], acc[0][nt][1], acc[0][nt][2], acc[0][nt][3],
                                b[s][0].x, b[s][0].y, b[s][0].z, b[s][0].w, w.x, w.y);
                        mma_f16(acc[1][nt][0], acc[1][nt][1], acc[1][nt][2], acc[1][nt][3],
                                b[s][1].x, b[s][1].y, b[s][1].z, b[s][1].w, w.x, w.y);
                    }
                }
            }

            barn(4, 256);                      // RshB data cols free
            #pragma unroll
            for (int mt = 0; mt < 2; mt++)
                #pragma unroll
                for (int nt = 0; nt < 4; nt++) {
                    int row = kq * 32 + mt * 16 + g;
                    RshB[row * RPK + nt * 4 + t]       = pack_h2(acc[mt][nt][0], acc[mt][nt][1]);
                    RshB[(row + 8) * RPK + nt * 4 + t] = pack_h2(acc[mt][nt][2], acc[mt][nt][3]);
                }
            barn(3, 256);                      // partials ready

            float s0 = bias1[0], s1 = bias1[1], s2 = bias1[2], s3 = bias1[3];
            const int sel = ej & 1;
            #pragma unroll
            for (int kk = 0; kk < 8; kk++) {
                const unsigned* rp = RshB + (kk * 32 + eb) * RPK + (ej >> 1);
                #pragma unroll
                for (int q = 0; q < 4; q++) {
                    __half2 hv = *(const __half2*)&rp[q * 4];
                    float2 f = __half22float2(hv);
                    float v = sel ? f.y : f.x;
                    if (q == 0) s0 += v; else if (q == 1) s1 += v;
                    else if (q == 2) s2 += v; else s3 += v;
                }
            }
            float iv = sigm(s0), fv = sigm(s1), gv = tanha(s2), ov = sigm(s3);
            c1_state = fv * c1_state + iv * gv;
            float h1val = ov * tanha(c1_state);
            unsigned hb = (unsigned)__half_as_ushort(__float2half_rn(h1val));
            unsigned ob = __shfl_xor_sync(0xffffffffu, hb, 1);
            if ((ej & 1) == 0)
                g_h1H[(r + 1) & 1][foff] = (hb & 0xffffu) | (ob << 16);
            // residual from hbuf hole, slot (r-1)&3
            {
                int d = (r - 1) & 3;
                const unsigned* hrow = (d < 2 ? RshA : RshB) + (d & 1) * 128 * RPK + hb_row;
                float h0_res = __half2float(((const __half*)hrow)[hb_sel]);
                outseq[((size_t)eb * T_ + (r - 1)) * H_ + hcol] = h1val + h0_res;
            }
            __syncwarp();
            if (lane == 0) flag_release_idx(g_f1, bid & 15);
        }
    }
}

// ---------------- launch ----------------
extern "C" void kernel_launch(void* const* d_in, const int* in_sizes, int n_in,
                              void* d_out, int out_size) {
    const float* x    = (const float*)d_in[0];
    const float* Wih0 = (const float*)d_in[1];
    const float* Whh0 = (const float*)d_in[2];
    const float* bih0 = (const float*)d_in[3];
    const float* bhh0 = (const float*)d_in[4];
    const float* Wih1 = (const float*)d_in[5];
    const float* Whh1 = (const float*)d_in[6];
    const float* bih1 = (const float*)d_in[7];
    const float* bhh1 = (const float*)d_in[8];
    float* out = (float*)d_out;

    cudaFuncSetAttribute(lstm_fused_kernel,
                         cudaFuncAttributeMaxDynamicSharedMemorySize, FUSED_SMEM);

    void* p;
    cudaGetSymbolAddress(&p, g_xg);  float* xg = (float*)p;
    cudaGetSymbolAddress(&p, g_f0);  unsigned* f0 = (unsigned*)p;
    cudaGetSymbolAddress(&p, g_f1);  unsigned* f1 = (unsigned*)p;

    dim3 gg(32, 128);

    cudaMemsetAsync(f0, 0, sizeof(unsigned) * NC0 * CSTR);
    cudaMemsetAsync(f1, 0, sizeof(unsigned) * NC1 * CSTR);
    gemm_xg_kernel<<<gg, 256>>>(x, Wih0, bih0, bhh0, xg);
    lstm_fused_kernel<<<NBLK, NTHR, FUSED_SMEM>>>(xg, Whh0, Wih1, Whh1, bih1, bhh1, out);
}

// round 16
// speedup vs baseline: 1.0294x; 1.0294x over previous
#include <cuda_runtime.h>
#include <cuda_fp16.h>
#include <cstdint>

#define B_  32
#define T_  512
#define H_  1024
#define G4_ 4096
#define M_  (B_ * T_)   // 16384
#define NBLK 128
#define NTHR 512
#define CSTR 64          // counter stride in u32 (256 B)
#define NC0  8           // f0 counters: stripe = bid>>4 (16 blocks each)
#define NC1  16          // f1 counters: stripe = bid&15 (8 blocks each)

// ---------------- static device scratch ----------------
__device__ float g_xg[(size_t)M_ * G4_];     // layer-0 gate preactivations (from GEMM0)
__device__ unsigned g_h0H[4][16384];         // frag-permuted fp16 h0, depth-4 (slot r&3)
__device__ unsigned g_h1H[2][16384];         // h1, parity
__device__ unsigned g_f0[NC0 * CSTR];        // h0-publish flags (per-warp release: +8/block/round)
__device__ unsigned g_f1[NC1 * CSTR];        // L1-done flags   (per-warp release: +8/block/round)

// ---------------- helpers ----------------
__device__ __forceinline__ void mma_f16(float& c0, float& c1, float& c2, float& c3,
                                        uint32_t a0, uint32_t a1, uint32_t a2, uint32_t a3,
                                        uint32_t b0, uint32_t b1) {
    asm volatile(
        "mma.sync.aligned.m16n8k16.row.col.f32.f16.f16.f32 "
        "{%0,%1,%2,%3},{%4,%5,%6,%7},{%8,%9},{%0,%1,%2,%3};"
        : "+f"(c0), "+f"(c1), "+f"(c2), "+f"(c3)
        : "r"(a0), "r"(a1), "r"(a2), "r"(a3), "r"(b0), "r"(b1));
}

__device__ __forceinline__ float tanha(float x) {
    float y;
    asm("tanh.approx.f32 %0, %1;" : "=f"(y) : "f"(x));
    return y;
}
__device__ __forceinline__ float sigm(float x) {
    return fmaf(tanha(0.5f * x), 0.5f, 0.5f);
}

__device__ __forceinline__ unsigned pack_h2(float a, float b) {
    __half2 h = __floats2half2_rn(a, b);
    return *(unsigned*)&h;
}

__device__ __forceinline__ void barn(int id, int cnt) {
    asm volatile("bar.sync %0, %1;" :: "r"(id), "r"(cnt) : "memory");
}

__device__ __forceinline__ void flag_release_idx(unsigned* base, int idx) {
    asm volatile("red.release.gpu.global.add.u32 [%0], 1;"
                 :: "l"(&base[idx * CSTR]) : "memory");
}

__device__ __forceinline__ void flag_poll(const unsigned* base, int idx, unsigned target) {
    const unsigned* cp = &base[idx * CSTR];
    unsigned v;
    asm volatile("ld.acquire.gpu.global.u32 %0, [%1];" : "=r"(v) : "l"(cp) : "memory");
    while (v < target) {
        __nanosleep(64);
        asm volatile("ld.acquire.gpu.global.u32 %0, [%1];" : "=r"(v) : "l"(cp) : "memory");
    }
}

// ---------------- big GEMM (fp16 mma): C[M,4096] = A[M,1024]*W^T + bias ----------------
#define GS_ 12

__global__ __launch_bounds__(256, 2)
void gemm_xg_kernel(const float* __restrict__ A,
                    const float* __restrict__ W,
                    const float* __restrict__ b0,
                    const float* __restrict__ b1,
                    float* __restrict__ C)
{
    __shared__ unsigned Ash[128 * GS_];
    __shared__ unsigned Bsh[128 * GS_];

    const int tid  = threadIdx.x;
    const int wid  = tid >> 5, lane = tid & 31;
    const int g    = lane >> 2, t = lane & 3;
    const int wm   = wid & 1, wn = wid >> 1;
    const int cm   = blockIdx.y * 128;
    const int cn   = blockIdx.x * 128;

    float acc[4][4][4];
    #pragma unroll
    for (int i = 0; i < 4; i++)
        #pragma unroll
        for (int j = 0; j < 4; j++)
            #pragma unroll
            for (int q = 0; q < 4; q++) acc[i][j][q] = 0.0f;

    const int r0 = tid >> 1;
    const int q0 = tid & 1;

    const float* Ag = A + (size_t)(cm + r0) * 1024 + 8 * q0;
    const float* Bg = W + (size_t)(cn + r0) * 1024 + 8 * q0;

    float4 av0 = *(const float4*)(Ag);
    float4 av1 = *(const float4*)(Ag + 4);
    float4 bv0 = *(const float4*)(Bg);
    float4 bv1 = *(const float4*)(Bg + 4);

    for (int kk = 0; kk < 1024; kk += 16) {
        __syncthreads();
        {
            uint4 pa, pb;
            pa.x = pack_h2(av0.x, av0.y); pa.y = pack_h2(av0.z, av0.w);
            pa.z = pack_h2(av1.x, av1.y); pa.w = pack_h2(av1.z, av1.w);
            pb.x = pack_h2(bv0.x, bv0.y); pb.y = pack_h2(bv0.z, bv0.w);
            pb.z = pack_h2(bv1.x, bv1.y); pb.w = pack_h2(bv1.z, bv1.w);
            *(uint4*)(Ash + r0 * GS_ + 4 * q0) = pa;
            *(uint4*)(Bsh + r0 * GS_ + 4 * q0) = pb;
        }
        __syncthreads();

        if (kk + 16 < 1024) {
            av0 = *(const float4*)(Ag + kk + 16);
            av1 = *(const float4*)(Ag + kk + 20);
            bv0 = *(const float4*)(Bg + kk + 16);
            bv1 = *(const float4*)(Bg + kk + 20);
        }

        uint32_t af[4][4];
        uint32_t bf[4][2];
        #pragma unroll
        for (int mt = 0; mt < 4; mt++) {
            int rb = wm * 64 + mt * 16;
            af[mt][0] = Ash[(rb + g)     * GS_ + t];
            af[mt][1] = Ash[(rb + g + 8) * GS_ + t];
            af[mt][2] = Ash[(rb + g)     * GS_ + t + 4];
            af[mt][3] = Ash[(rb + g + 8) * GS_ + t + 4];
        }
        #pragma unroll
        for (int nt = 0; nt < 4; nt++) {
            int nb = wn * 32 + nt * 8 + g;
            bf[nt][0] = Bsh[nb * GS_ + t];
            bf[nt][1] = Bsh[nb * GS_ + t + 4];
        }
        #pragma unroll
        for (int mt = 0; mt < 4; mt++)
            #pragma unroll
            for (int nt = 0; nt < 4; nt++)
                mma_f16(acc[mt][nt][0], acc[mt][nt][1], acc[mt][nt][2], acc[mt][nt][3],
                        af[mt][0], af[mt][1], af[mt][2], af[mt][3],
                        bf[nt][0], bf[nt][1]);
    }

    #pragma unroll
    for (int mt = 0; mt < 4; mt++) {
        #pragma unroll
        for (int nt = 0; nt < 4; nt++) {
            int m = cm + wm * 64 + mt * 16 + g;
            int n = cn + wn * 32 + nt * 8 + 2 * t;
            float bs0 = b0[n] + b1[n];
            float bs1 = b0[n + 1] + b1[n + 1];
            float2 v0 = make_float2(acc[mt][nt][0] + bs0, acc[mt][nt][1] + bs1);
            float2 v1 = make_float2(acc[mt][nt][2] + bs0, acc[mt][nt][3] + bs1);
            *(float2*)(C + (size_t)m * G4_ + n) = v0;
            *(float2*)(C + (size_t)(m + 8) * G4_ + n) = v1;
        }
    }
}

// ---------------- fused two-layer scan, per-warp producer-aligned dataflow ----------------
// Warps 8-15 = layer-0 (critical path); warps 0-7 = layer-1.
// R14 configuration (L1: 2-chunk double-buffered loads, 32 regs) + merged L0 polls.
#define WA_  16384
#define WB_  32768
#define RPK  17
#define RPKS (8 * 32 * RPK)
#define FUSED_SMEM ((WA_ + WB_ + 2 * RPKS) * 4)   // 231424 B (hbuf lives in RPK holes)

__global__ __launch_bounds__(NTHR, 1)
void lstm_fused_kernel(const float* __restrict__ xg,
                       const float* __restrict__ Whh0,
                       const float* __restrict__ Wih1,
                       const float* __restrict__ Whh1,
                       const float* __restrict__ bih1,
                       const float* __restrict__ bhh1,
                       float* __restrict__ outseq)
{
    extern __shared__ unsigned smu[];
    unsigned* WshA = smu;
    unsigned* WshB = smu + WA_;
    unsigned* RshA = smu + WA_ + WB_;
    unsigned* RshB = RshA + RPKS;

    const int tid  = threadIdx.x;
    const int bid  = blockIdx.x;
    const int wid  = tid >> 5, lane = tid & 31;
    const int g    = lane >> 2, t = lane & 3;

    // ---- fill Whh0 frags ----
    for (int e = tid; e < WA_; e += NTHR) {
        int rr = e & 1;
        int ln = (e >> 1) & 31;
        int nt = (e >> 6) & 3;
        int si = (e >> 8) & 7;
        int kq = e >> 11;
        int n8 = ln >> 2, tt = ln & 3;
        int row = nt * 1024 + bid * 8 + n8;
        int k0  = kq * 128 + si * 16 + 2 * tt + rr * 8;
        WshA[e] = pack_h2(Whh0[(size_t)row * 1024 + k0],
                          Whh0[(size_t)row * 1024 + k0 + 1]);
    }
    // ---- fill [Wih1|Whh1] frags (K=2048) ----
    for (int e = tid; e < WB_; e += NTHR) {
        int rr = e & 1;
        int ln = (e >> 1) & 31;
        int nt = (e >> 6) & 3;
        int si = (e >> 8) & 15;
        int kq = e >> 12;
        int n8 = ln >> 2, tt = ln & 3;
        int row = nt * 1024 + bid * 8 + n8;
        int kg  = kq * 256 + si * 16 + 2 * tt + rr * 8;
        const float* src = (kg < 1024) ? (Wih1 + (size_t)row * 1024 + kg)
                                       : (Whh1 + (size_t)row * 1024 + (kg - 1024));
        WshB[e] = pack_h2(src[0], src[1]);
    }

    const int cix  = tid & 255;
    const int eb   = cix >> 3;
    const int ej   = cix & 7;
    const int hcol = bid * 8 + ej;
    const int c_   = bid >> 1;
    const int fmt  = eb >> 4;
    const int ridx = (bid & 1) * 2 + ((eb >> 3) & 1);
    const int foff = (((c_ * 2 + fmt) * 32) + (eb & 7) * 4 + (ej >> 1)) * 4 + ridx;

    // hbuf slot d (0..3) lives in the RPK padding holes (col 16)
    const int hb_row = (cix >> 1) * RPK + 16;
    const int hb_sel = cix & 1;

    float c0_state = 0.0f, c1_state = 0.0f;
    float bias1[4];
    if (tid >= 256) {                           // L0 half
        if ((ej & 1) == 0) g_h0H[3][foff] = 0u; // h0[-1] -> slot 3
    } else {                                    // L1 half
        #pragma unroll
        for (int q = 0; q < 4; q++)
            bias1[q] = bih1[q * 1024 + hcol] + bhh1[q * 1024 + hcol];
        if ((ej & 1) == 0) g_h1H[1][foff] = 0u; // h1[-1] -> parity 1
    }

    // init publish: every L0 warp releases once
    __syncthreads();
    if (tid >= 256 && lane == 0) flag_release_idx(g_f0, bid >> 4);

    if (tid >= 256) {
        // ================= layer-0 chain (warps 8-15) =================
        const int kq = wid - 8;
        for (int r = 0; r < T_; r++) {
            // prefetch xg (independent of flags)
            const float* xp = xg + ((size_t)eb * T_ + r) * G4_ + hcol;
            float xv0 = __ldcs(xp);
            float xv1 = __ldcs(xp + 1024);
            float xv2 = __ldcs(xp + 2048);
            float xv3 = __ldcs(xp + 3072);

            // merged waits: lane0 -> my 16 producers' h0[r-1]; lanes 16.. -> L1 antidep (lag<=2)
            if (lane == 0) flag_poll(g_f0, kq, (unsigned)(r + 1) * 128u);
            else if (lane >= 16 && r >= 3)
                flag_poll(g_f1, lane - 16, (unsigned)(r - 2) * 64u);
            __syncwarp();

            float acc[2][4][4];
            #pragma unroll
            for (int mt = 0; mt < 2; mt++)
                #pragma unroll
                for (int nt = 0; nt < 4; nt++)
                    #pragma unroll
                    for (int q = 0; q < 4; q++) acc[mt][nt][q] = 0.0f;

            const uint4* hA = (const uint4*)g_h0H[(r + 3) & 3];   // h0[r-1]
            uint4 a[2][4][2];
            #pragma unroll
            for (int h2 = 0; h2 < 2; h2++)
                #pragma unroll
                for (int s = 0; s < 4; s++) {
                    int c = kq * 8 + h2 * 4 + s;
                    a[h2][s][0] = __ldcg(hA + (c * 2 + 0) * 32 + lane);
                    a[h2][s][1] = __ldcg(hA + (c * 2 + 1) * 32 + lane);
                }
            #pragma unroll
            for (int h2 = 0; h2 < 2; h2++)
                #pragma unroll
                for (int s = 0; s < 4; s++) {
                    int si = h2 * 4 + s;
                    #pragma unroll
                    for (int nt = 0; nt < 4; nt++) {
                        uint2 w = *(const uint2*)(WshA + (((kq * 8 + si) * 4 + nt) << 6) + lane * 2);
                        mma_f16(acc[0][nt][0], acc[0][nt][1], acc[0][nt][2], acc[0][nt][3],
                                a[h2][s][0].x, a[h2][s][0].y, a[h2][s][0].z, a[h2][s][0].w, w.x, w.y);
                        mma_f16(acc[1][nt][0], acc[1][nt][1], acc[1][nt][2], acc[1][nt][3],
                                a[h2][s][1].x, a[h2][s][1].y, a[h2][s][1].z, a[h2][s][1].w, w.x, w.y);
                    }
                }

            barn(2, 256);                      // RshA free (prev round's reduce done)
            #pragma unroll
            for (int mt = 0; mt < 2; mt++)
                #pragma unroll
                for (int nt = 0; nt < 4; nt++) {
                    int row = kq * 32 + mt * 16 + g;
                    RshA[row * RPK + nt * 4 + t]       = pack_h2(acc[mt][nt][0], acc[mt][nt][1]);
                    RshA[(row + 8) * RPK + nt * 4 + t] = pack_h2(acc[mt][nt][2], acc[mt][nt][3]);
                }
            barn(1, 256);                      // partials ready

            float s0 = xv0, s1 = xv1, s2 = xv2, s3 = xv3;
            const int sel = ej & 1;
            #pragma unroll
            for (int kk = 0; kk < 8; kk++) {
                const unsigned* rp = RshA + (kk * 32 + eb) * RPK + (ej >> 1);
                #pragma unroll
                for (int q = 0; q < 4; q++) {
                    __half2 hv = *(const __half2*)&rp[q * 4];
                    float2 f = __half22float2(hv);
                    float v = sel ? f.y : f.x;
                    if (q == 0) s0 += v; else if (q == 1) s1 += v;
                    else if (q == 2) s2 += v; else s3 += v;
                }
            }
            float iv = sigm(s0), fv = sigm(s1), gv = tanha(s2), ov = sigm(s3);
            c0_state = fv * c0_state + iv * gv;
            float hval = ov * tanha(c0_state);

            // publish h0[r] (frag-permuted fp16) + residual into hbuf hole
            unsigned hb = (unsigned)__half_as_ushort(__float2half_rn(hval));
            unsigned ob = __shfl_xor_sync(0xffffffffu, hb, 1);
            int d = r & 3;
            if ((ej & 1) == 0)
                g_h0H[d][foff] = (hb & 0xffffu) | (ob << 16);
            {
                unsigned* hrow = (d < 2 ? RshA : RshB) + (d & 1) * 128 * RPK + hb_row;
                ((__half*)hrow)[hb_sel] = __float2half_rn(hval);
            }
            __syncwarp();
            if (lane == 0) flag_release_idx(g_f0, bid >> 4);
        }
    } else {
        // ================= layer-1 chain (warps 0-7) =================
        const int kq = wid;
        for (int r = 1; r <= T_; r++) {
            // per-warp waits
            if (kq < 4) {
                if (lane < 2) flag_poll(g_f0, 2 * kq + lane, (unsigned)(r + 1) * 128u);
            } else {
                if (r == 1) { if (lane < NC0) flag_poll(g_f0, lane, 2u * 128u); }
                else        { if (lane < NC1) flag_poll(g_f1, lane, (unsigned)(r - 1) * 64u); }
            }
            __syncwarp();

            float acc[2][4][4];
            #pragma unroll
            for (int mt = 0; mt < 2; mt++)
                #pragma unroll
                for (int nt = 0; nt < 4; nt++)
                    #pragma unroll
                    for (int q = 0; q < 4; q++) acc[mt][nt][q] = 0.0f;

            const uint4* baseA;
            int cb;
            if (kq < 4) { baseA = (const uint4*)g_h0H[(r + 3) & 3]; cb = kq * 16; }       // h0[r-1]
            else        { baseA = (const uint4*)g_h1H[r & 1];       cb = (kq - 4) * 16; } // h1[r-2]

            uint4 b[2][2][2];
            #pragma unroll
            for (int s = 0; s < 2; s++) {
                int c = cb + s;
                b[0][s][0] = __ldcg(baseA + (c * 2 + 0) * 32 + lane);
                b[0][s][1] = __ldcg(baseA + (c * 2 + 1) * 32 + lane);
            }
            #pragma unroll
            for (int wv = 0; wv < 8; wv++) {
                int cur = wv & 1;
                if (wv < 7) {
                    #pragma unroll
                    for (int s = 0; s < 2; s++) {
                        int c = cb + (wv + 1) * 2 + s;
                        b[1 - cur][s][0] = __ldcg(baseA + (c * 2 + 0) * 32 + lane);
                        b[1 - cur][s][1] = __ldcg(baseA + (c * 2 + 1) * 32 + lane);
                    }
                }
                #pragma unroll
                for (int s = 0; s < 2; s++) {
                    int si = wv * 2 + s;
                    #pragma unroll
                    for (int nt = 0; nt < 4; nt++) {
                        uint2 w = *(const uint2*)(WshB + (((kq * 16 + si) * 4 + nt) << 6) + lane * 2);
                        mma_f16(acc[0][nt][0], acc[0][nt][1], acc[0][nt][2], acc[0][nt][3],
                                b[cur][s][0].x, b[cur][s][0].y, b[cur][s][0].z, b[cur][s][0].w, w.x, w.y);
                        mma_f16(acc[1][nt][0], acc[1][nt][1], acc[1][nt][2], acc[1][nt][3],
                                b[cur][s][1].x, b[cur][s][1].y, b[cur][s][1].z, b[cur][s][1].w, w.x, w.y);
                    }
                }
            }

            barn(4, 256);                      // RshB data cols free
            #pragma unroll
            for (int mt = 0; mt < 2; mt++)
                #pragma unroll
                for (int nt = 0; nt < 4; nt++) {
                    int row = kq * 32 + mt * 16 + g;
                    RshB[row * RPK + nt * 4 + t]       = pack_h2(acc[mt][nt][0], acc[mt][nt][1]);
                    RshB[(row + 8) * RPK + nt * 4 + t] = pack_h2(acc[mt][nt][2], acc[mt][nt][3]);
                }
            barn(3, 256);                      // partials ready

            float s0 = bias1[0], s1 = bias1[1], s2 = bias1[2], s3 = bias1[3];
            const int sel = ej & 1;
            #pragma unroll
            for (int kk = 0; kk < 8; kk++) {
                const unsigned* rp = RshB + (kk * 32 + eb) * RPK + (ej >> 1);
                #pragma unroll
                for (int q = 0; q < 4; q++) {
                    __half2 hv = *(const __half2*)&rp[q * 4];
                    float2 f = __half22float2(hv);
                    float v = sel ? f.y : f.x;
                    if (q == 0) s0 += v; else if (q == 1) s1 += v;
                    else if (q == 2) s2 += v; else s3 += v;
                }
            }
            float iv = sigm(s0), fv = sigm(s1), gv = tanha(s2), ov = sigm(s3);
            c1_state = fv * c1_state + iv * gv;
            float h1val = ov * tanha(c1_state);
            unsigned hb = (unsigned)__half_as_ushort(__float2half_rn(h1val));
            unsigned ob = __shfl_xor_sync(0xffffffffu, hb, 1);
            if ((ej & 1) == 0)
                g_h1H[(r + 1) & 1][foff] = (hb & 0xffffu) | (ob << 16);
            // residual from hbuf hole, slot (r-1)&3
            {
                int d = (r - 1) & 3;
                const unsigned* hrow = (d < 2 ? RshA : RshB) + (d & 1) * 128 * RPK + hb_row;
                float h0_res = __half2float(((const __half*)hrow)[hb_sel]);
                outseq[((size_t)eb * T_ + (r - 1)) * H_ + hcol] = h1val + h0_res;
            }
            __syncwarp();
            if (lane == 0) flag_release_idx(g_f1, bid & 15);
        }
    }
}

// ---------------- launch ----------------
extern "C" void kernel_launch(void* const* d_in, const int* in_sizes, int n_in,
                              void* d_out, int out_size) {
    const float* x    = (const float*)d_in[0];
    const float* Wih0 = (const float*)d_in[1];
    const float* Whh0 = (const float*)d_in[2];
    const float* bih0 = (const float*)d_in[3];
    const float* bhh0 = (const float*)d_in[4];
    const float* Wih1 = (const float*)d_in[5];
    const float* Whh1 = (const float*)d_in[6];
    const float* bih1 = (const float*)d_in[7];
    const float* bhh1 = (const float*)d_in[8];
    float* out = (float*)d_out;

    cudaFuncSetAttribute(lstm_fused_kernel,
                         cudaFuncAttributeMaxDynamicSharedMemorySize, FUSED_SMEM);

    void* p;
    cudaGetSymbolAddress(&p, g_xg);  float* xg = (float*)p;
    cudaGetSymbolAddress(&p, g_f0);  unsigned* f0 = (unsigned*)p;
    cudaGetSymbolAddress(&p, g_f1);  unsigned* f1 = (unsigned*)p;

    dim3 gg(32, 128);

    cudaMemsetAsync(f0, 0, sizeof(unsigned) * NC0 * CSTR);
    cudaMemsetAsync(f1, 0, sizeof(unsigned) * NC1 * CSTR);
    gemm_xg_kernel<<<gg, 256>>>(x, Wih0, bih0, bhh0, xg);
    lstm_fused_kernel<<<NBLK, NTHR, FUSED_SMEM>>>(xg, Whh0, Wih1, Whh1, bih1, bhh1, out);
}

// round 17
// speedup vs baseline: 1.2723x; 1.2360x over previous
#include <cuda_runtime.h>
#include <cuda_fp16.h>
#include <cstdint>

#define B_  32
#define T_  512
#define H_  1024
#define G4_ 4096
#define M_  (B_ * T_)   // 16384
#define NBLK 128
#define NTHR 512
#define CSTR 64          // counter stride in u32 (256 B)
#define NC0  8           // f0 counters: stripe = bid>>4 (16 blocks each)
#define NC1  16          // f1 counters: stripe = bid&15 (8 blocks each)

// ---------------- static device scratch ----------------
__device__ float g_xg[(size_t)M_ * G4_];     // layer-0 gate preactivations (from GEMM0)
__device__ unsigned g_h0H[4][16384];         // frag-permuted fp16 h0, depth-4 (slot r&3)
__device__ unsigned g_h1H[2][16384];         // h1, parity
__device__ unsigned g_f0[NC0 * CSTR];        // h0-publish flags (per-warp release: +8/block/round)
__device__ unsigned g_f1[NC1 * CSTR];        // L1-done flags   (per-warp release: +8/block/round)

// ---------------- helpers ----------------
__device__ __forceinline__ void mma_f16(float& c0, float& c1, float& c2, float& c3,
                                        uint32_t a0, uint32_t a1, uint32_t a2, uint32_t a3,
                                        uint32_t b0, uint32_t b1) {
    asm volatile(
        "mma.sync.aligned.m16n8k16.row.col.f32.f16.f16.f32 "
        "{%0,%1,%2,%3},{%4,%5,%6,%7},{%8,%9},{%0,%1,%2,%3};"
        : "+f"(c0), "+f"(c1), "+f"(c2), "+f"(c3)
        : "r"(a0), "r"(a1), "r"(a2), "r"(a3), "r"(b0), "r"(b1));
}

__device__ __forceinline__ float tanha(float x) {
    float y;
    asm("tanh.approx.f32 %0, %1;" : "=f"(y) : "f"(x));
    return y;
}
__device__ __forceinline__ float sigm(float x) {
    return fmaf(tanha(0.5f * x), 0.5f, 0.5f);
}

__device__ __forceinline__ unsigned pack_h2(float a, float b) {
    __half2 h = __floats2half2_rn(a, b);
    return *(unsigned*)&h;
}

__device__ __forceinline__ void barn(int id, int cnt) {
    asm volatile("bar.sync %0, %1;" :: "r"(id), "r"(cnt) : "memory");
}

__device__ __forceinline__ void flag_release_idx(unsigned* base, int idx) {
    asm volatile("red.release.gpu.global.add.u32 [%0], 1;"
                 :: "l"(&base[idx * CSTR]) : "memory");
}

__device__ __forceinline__ void flag_poll(const unsigned* base, int idx, unsigned target) {
    const unsigned* cp = &base[idx * CSTR];
    unsigned v;
    asm volatile("ld.acquire.gpu.global.u32 %0, [%1];" : "=r"(v) : "l"(cp) : "memory");
    while (v < target) {
        __nanosleep(64);
        asm volatile("ld.acquire.gpu.global.u32 %0, [%1];" : "=r"(v) : "l"(cp) : "memory");
    }
}

// ---------------- big GEMM (fp16 mma): C[M,4096] = A[M,1024]*W^T + bias ----------------
#define GS_ 12

__global__ __launch_bounds__(256, 2)
void gemm_xg_kernel(const float* __restrict__ A,
                    const float* __restrict__ W,
                    const float* __restrict__ b0,
                    const float* __restrict__ b1,
                    float* __restrict__ C)
{
    __shared__ unsigned Ash[128 * GS_];
    __shared__ unsigned Bsh[128 * GS_];

    const int tid  = threadIdx.x;
    const int wid  = tid >> 5, lane = tid & 31;
    const int g    = lane >> 2, t = lane & 3;
    const int wm   = wid & 1, wn = wid >> 1;
    const int cm   = blockIdx.y * 128;
    const int cn   = blockIdx.x * 128;

    float acc[4][4][4];
    #pragma unroll
    for (int i = 0; i < 4; i++)
        #pragma unroll
        for (int j = 0; j < 4; j++)
            #pragma unroll
            for (int q = 0; q < 4; q++) acc[i][j][q] = 0.0f;

    const int r0 = tid >> 1;
    const int q0 = tid & 1;

    const float* Ag = A + (size_t)(cm + r0) * 1024 + 8 * q0;
    const float* Bg = W + (size_t)(cn + r0) * 1024 + 8 * q0;

    float4 av0 = *(const float4*)(Ag);
    float4 av1 = *(const float4*)(Ag + 4);
    float4 bv0 = *(const float4*)(Bg);
    float4 bv1 = *(const float4*)(Bg + 4);

    for (int kk = 0; kk < 1024; kk += 16) {
        __syncthreads();
        {
            uint4 pa, pb;
            pa.x = pack_h2(av0.x, av0.y); pa.y = pack_h2(av0.z, av0.w);
            pa.z = pack_h2(av1.x, av1.y); pa.w = pack_h2(av1.z, av1.w);
            pb.x = pack_h2(bv0.x, bv0.y); pb.y = pack_h2(bv0.z, bv0.w);
            pb.z = pack_h2(bv1.x, bv1.y); pb.w = pack_h2(bv1.z, bv1.w);
            *(uint4*)(Ash + r0 * GS_ + 4 * q0) = pa;
            *(uint4*)(Bsh + r0 * GS_ + 4 * q0) = pb;
        }
        __syncthreads();

        if (kk + 16 < 1024) {
            av0 = *(const float4*)(Ag + kk + 16);
            av1 = *(const float4*)(Ag + kk + 20);
            bv0 = *(const float4*)(Bg + kk + 16);
            bv1 = *(const float4*)(Bg + kk + 20);
        }

        uint32_t af[4][4];
        uint32_t bf[4][2];
        #pragma unroll
        for (int mt = 0; mt < 4; mt++) {
            int rb = wm * 64 + mt * 16;
            af[mt][0] = Ash[(rb + g)     * GS_ + t];
            af[mt][1] = Ash[(rb + g + 8) * GS_ + t];
            af[mt][2] = Ash[(rb + g)     * GS_ + t + 4];
            af[mt][3] = Ash[(rb + g + 8) * GS_ + t + 4];
        }
        #pragma unroll
        for (int nt = 0; nt < 4; nt++) {
            int nb = wn * 32 + nt * 8 + g;
            bf[nt][0] = Bsh[nb * GS_ + t];
            bf[nt][1] = Bsh[nb * GS_ + t + 4];
        }
        #pragma unroll
        for (int mt = 0; mt < 4; mt++)
            #pragma unroll
            for (int nt = 0; nt < 4; nt++)
                mma_f16(acc[mt][nt][0], acc[mt][nt][1], acc[mt][nt][2], acc[mt][nt][3],
                        af[mt][0], af[mt][1], af[mt][2], af[mt][3],
                        bf[nt][0], bf[nt][1]);
    }

    #pragma unroll
    for (int mt = 0; mt < 4; mt++) {
        #pragma unroll
        for (int nt = 0; nt < 4; nt++) {
            int m = cm + wm * 64 + mt * 16 + g;
            int n = cn + wn * 32 + nt * 8 + 2 * t;
            float bs0 = b0[n] + b1[n];
            float bs1 = b0[n + 1] + b1[n + 1];
            float2 v0 = make_float2(acc[mt][nt][0] + bs0, acc[mt][nt][1] + bs1);
            float2 v1 = make_float2(acc[mt][nt][2] + bs0, acc[mt][nt][3] + bs1);
            *(float2*)(C + (size_t)m * G4_ + n) = v0;
            *(float2*)(C + (size_t)(m + 8) * G4_ + n) = v1;
        }
    }
}

// ---------------- fused two-layer scan, per-warp producer-aligned dataflow ----------------
// EXACT R14 protocol: L0 polls ONLY its f0 stripe before GEMM; the f1 anti-dep
// poll sits after the cell computation (just before publish) where it is free.
#define WA_  16384
#define WB_  32768
#define RPK  17
#define RPKS (8 * 32 * RPK)
#define FUSED_SMEM ((WA_ + WB_ + 2 * RPKS) * 4)   // 231424 B (hbuf lives in RPK holes)

__global__ __launch_bounds__(NTHR, 1)
void lstm_fused_kernel(const float* __restrict__ xg,
                       const float* __restrict__ Whh0,
                       const float* __restrict__ Wih1,
                       const float* __restrict__ Whh1,
                       const float* __restrict__ bih1,
                       const float* __restrict__ bhh1,
                       float* __restrict__ outseq)
{
    extern __shared__ unsigned smu[];
    unsigned* WshA = smu;
    unsigned* WshB = smu + WA_;
    unsigned* RshA = smu + WA_ + WB_;
    unsigned* RshB = RshA + RPKS;

    const int tid  = threadIdx.x;
    const int bid  = blockIdx.x;
    const int wid  = tid >> 5, lane = tid & 31;
    const int g    = lane >> 2, t = lane & 3;

    // ---- fill Whh0 frags ----
    for (int e = tid; e < WA_; e += NTHR) {
        int rr = e & 1;
        int ln = (e >> 1) & 31;
        int nt = (e >> 6) & 3;
        int si = (e >> 8) & 7;
        int kq = e >> 11;
        int n8 = ln >> 2, tt = ln & 3;
        int row = nt * 1024 + bid * 8 + n8;
        int k0  = kq * 128 + si * 16 + 2 * tt + rr * 8;
        WshA[e] = pack_h2(Whh0[(size_t)row * 1024 + k0],
                          Whh0[(size_t)row * 1024 + k0 + 1]);
    }
    // ---- fill [Wih1|Whh1] frags (K=2048) ----
    for (int e = tid; e < WB_; e += NTHR) {
        int rr = e & 1;
        int ln = (e >> 1) & 31;
        int nt = (e >> 6) & 3;
        int si = (e >> 8) & 15;
        int kq = e >> 12;
        int n8 = ln >> 2, tt = ln & 3;
        int row = nt * 1024 + bid * 8 + n8;
        int kg  = kq * 256 + si * 16 + 2 * tt + rr * 8;
        const float* src = (kg < 1024) ? (Wih1 + (size_t)row * 1024 + kg)
                                       : (Whh1 + (size_t)row * 1024 + (kg - 1024));
        WshB[e] = pack_h2(src[0], src[1]);
    }

    const int cix  = tid & 255;
    const int eb   = cix >> 3;
    const int ej   = cix & 7;
    const int hcol = bid * 8 + ej;
    const int c_   = bid >> 1;
    const int fmt  = eb >> 4;
    const int ridx = (bid & 1) * 2 + ((eb >> 3) & 1);
    const int foff = (((c_ * 2 + fmt) * 32) + (eb & 7) * 4 + (ej >> 1)) * 4 + ridx;

    // hbuf slot d (0..3) lives in the RPK padding holes (col 16)
    const int hb_row = (cix >> 1) * RPK + 16;
    const int hb_sel = cix & 1;

    float c0_state = 0.0f, c1_state = 0.0f;
    float bias1[4];
    if (tid >= 256) {                           // L0 half
        if ((ej & 1) == 0) g_h0H[3][foff] = 0u; // h0[-1] -> slot 3
    } else {                                    // L1 half
        #pragma unroll
        for (int q = 0; q < 4; q++)
            bias1[q] = bih1[q * 1024 + hcol] + bhh1[q * 1024 + hcol];
        if ((ej & 1) == 0) g_h1H[1][foff] = 0u; // h1[-1] -> parity 1
    }

    // init publish: every L0 warp releases once
    __syncthreads();
    if (tid >= 256 && lane == 0) flag_release_idx(g_f0, bid >> 4);

    if (tid >= 256) {
        // ================= layer-0 chain (warps 8-15) =================
        const int kq = wid - 8;
        for (int r = 0; r < T_; r++) {
            // prefetch xg (independent of flags)
            const float* xp = xg + ((size_t)eb * T_ + r) * G4_ + hcol;
            float xv0 = __ldcs(xp);
            float xv1 = __ldcs(xp + 1024);
            float xv2 = __ldcs(xp + 2048);
            float xv3 = __ldcs(xp + 3072);

            // per-warp wait: only MY 16 producers (stripe kq) must have published h0[r-1]
            if (lane == 0) flag_poll(g_f0, kq, (unsigned)(r + 1) * 128u);
            __syncwarp();

            float acc[2][4][4];
            #pragma unroll
            for (int mt = 0; mt < 2; mt++)
                #pragma unroll
                for (int nt = 0; nt < 4; nt++)
                    #pragma unroll
                    for (int q = 0; q < 4; q++) acc[mt][nt][q] = 0.0f;

            const uint4* hA = (const uint4*)g_h0H[(r + 3) & 3];   // h0[r-1]
            uint4 a[2][4][2];
            #pragma unroll
            for (int h2 = 0; h2 < 2; h2++)
                #pragma unroll
                for (int s = 0; s < 4; s++) {
                    int c = kq * 8 + h2 * 4 + s;
                    a[h2][s][0] = __ldcg(hA + (c * 2 + 0) * 32 + lane);
                    a[h2][s][1] = __ldcg(hA + (c * 2 + 1) * 32 + lane);
                }
            #pragma unroll
            for (int h2 = 0; h2 < 2; h2++)
                #pragma unroll
                for (int s = 0; s < 4; s++) {
                    int si = h2 * 4 + s;
                    #pragma unroll
                    for (int nt = 0; nt < 4; nt++) {
                        uint2 w = *(const uint2*)(WshA + (((kq * 8 + si) * 4 + nt) << 6) + lane * 2);
                        mma_f16(acc[0][nt][0], acc[0][nt][1], acc[0][nt][2], acc[0][nt][3],
                                a[h2][s][0].x, a[h2][s][0].y, a[h2][s][0].z, a[h2][s][0].w, w.x, w.y);
                        mma_f16(acc[1][nt][0], acc[1][nt][1], acc[1][nt][2], acc[1][nt][3],
                                a[h2][s][1].x, a[h2][s][1].y, a[h2][s][1].z, a[h2][s][1].w, w.x, w.y);
                    }
                }

            barn(2, 256);                      // RshA free (prev round's reduce done)
            #pragma unroll
            for (int mt = 0; mt < 2; mt++)
                #pragma unroll
                for (int nt = 0; nt < 4; nt++) {
                    int row = kq * 32 + mt * 16 + g;
                    RshA[row * RPK + nt * 4 + t]       = pack_h2(acc[mt][nt][0], acc[mt][nt][1]);
                    RshA[(row + 8) * RPK + nt * 4 + t] = pack_h2(acc[mt][nt][2], acc[mt][nt][3]);
                }
            barn(1, 256);                      // partials ready

            float s0 = xv0, s1 = xv1, s2 = xv2, s3 = xv3;
            const int sel = ej & 1;
            #pragma unroll
            for (int kk = 0; kk < 8; kk++) {
                const unsigned* rp = RshA + (kk * 32 + eb) * RPK + (ej >> 1);
                #pragma unroll
                for (int q = 0; q < 4; q++) {
                    __half2 hv = *(const __half2*)&rp[q * 4];
                    float2 f = __half22float2(hv);
                    float v = sel ? f.y : f.x;
                    if (q == 0) s0 += v; else if (q == 1) s1 += v;
                    else if (q == 2) s2 += v; else s3 += v;
                }
            }
            float iv = sigm(s0), fv = sigm(s1), gv = tanha(s2), ov = sigm(s3);
            c0_state = fv * c0_state + iv * gv;
            float hval = ov * tanha(c0_state);

            // anti-dependency: before overwriting slot r&3 / hbuf, all L1 rounds <= r-2 done
            if (r >= 3 && lane < NC1)
                flag_poll(g_f1, lane, (unsigned)(r - 2) * 64u);
            __syncwarp();

            // publish h0[r] (frag-permuted fp16) + residual into hbuf hole
            unsigned hb = (unsigned)__half_as_ushort(__float2half_rn(hval));
            unsigned ob = __shfl_xor_sync(0xffffffffu, hb, 1);
            int d = r & 3;
            if ((ej & 1) == 0)
                g_h0H[d][foff] = (hb & 0xffffu) | (ob << 16);
            {
                unsigned* hrow = (d < 2 ? RshA : RshB) + (d & 1) * 128 * RPK + hb_row;
                ((__half*)hrow)[hb_sel] = __float2half_rn(hval);
            }
            __syncwarp();
            if (lane == 0) flag_release_idx(g_f0, bid >> 4);
        }
    } else {
        // ================= layer-1 chain (warps 0-7) =================
        const int kq = wid;
        for (int r = 1; r <= T_; r++) {
            // per-warp waits
            if (kq < 4) {
                if (lane < 2) flag_poll(g_f0, 2 * kq + lane, (unsigned)(r + 1) * 128u);
            } else {
                if (r == 1) { if (lane < NC0) flag_poll(g_f0, lane, 2u * 128u); }
                else        { if (lane < NC1) flag_poll(g_f1, lane, (unsigned)(r - 1) * 64u); }
            }
            __syncwarp();

            float acc[2][4][4];
            #pragma unroll
            for (int mt = 0; mt < 2; mt++)
                #pragma unroll
                for (int nt = 0; nt < 4; nt++)
                    #pragma unroll
                    for (int q = 0; q < 4; q++) acc[mt][nt][q] = 0.0f;

            const uint4* baseA;
            int cb;
            if (kq < 4) { baseA = (const uint4*)g_h0H[(r + 3) & 3]; cb = kq * 16; }       // h0[r-1]
            else        { baseA = (const uint4*)g_h1H[r & 1];       cb = (kq - 4) * 16; } // h1[r-2]

            uint4 b[2][2][2];
            #pragma unroll
            for (int s = 0; s < 2; s++) {
                int c = cb + s;
                b[0][s][0] = __ldcg(baseA + (c * 2 + 0) * 32 + lane);
                b[0][s][1] = __ldcg(baseA + (c * 2 + 1) * 32 + lane);
            }
            #pragma unroll
            for (int wv = 0; wv < 8; wv++) {
                int cur = wv & 1;
                if (wv < 7) {
                    #pragma unroll
                    for (int s = 0; s < 2; s++) {
                        int c = cb + (wv + 1) * 2 + s;
                        b[1 - cur][s][0] = __ldcg(baseA + (c * 2 + 0) * 32 + lane);
                        b[1 - cur][s][1] = __ldcg(baseA + (c * 2 + 1) * 32 + lane);
                    }
                }
                #pragma unroll
                for (int s = 0; s < 2; s++) {
                    int si = wv * 2 + s;
                    #pragma unroll
                    for (int nt = 0; nt < 4; nt++) {
                        uint2 w = *(const uint2*)(WshB + (((kq * 16 + si) * 4 + nt) << 6) + lane * 2);
                        mma_f16(acc[0][nt][0], acc[0][nt][1], acc[0][nt][2], acc[0][nt][3],
                                b[cur][s][0].x, b[cur][s][0].y, b[cur][s][0].z, b[cur][s][0].w, w.x, w.y);
                        mma_f16(acc[1][nt][0], acc[1][nt][1], acc[1][nt][2], acc[1][nt][3],
                                b[cur][s][1].x, b[cur][s][1].y, b[cur][s][1].z, b[cur][s][1].w, w.x, w.y);
                    }
                }
            }

            barn(4, 256);                      // RshB data cols free
            #pragma unroll
            for (int mt = 0; mt < 2; mt++)
                #pragma unroll
                for (int nt = 0; nt < 4; nt++) {
                    int row = kq * 32 + mt * 16 + g;
                    RshB[row * RPK + nt * 4 + t]       = pack_h2(acc[mt][nt][0], acc[mt][nt][1]);
                    RshB[(row + 8) * RPK + nt * 4 + t] = pack_h2(acc[mt][nt][2], acc[mt][nt][3]);
                }
            barn(3, 256);                      // partials ready

            float s0 = bias1[0], s1 = bias1[1], s2 = bias1[2], s3 = bias1[3];
            const int sel = ej & 1;
            #pragma unroll
            for (int kk = 0; kk < 8; kk++) {
                const unsigned* rp = RshB + (kk * 32 + eb) * RPK + (ej >> 1);
                #pragma unroll
                for (int q = 0; q < 4; q++) {
                    __half2 hv = *(const __half2*)&rp[q * 4];
                    float2 f = __half22float2(hv);
                    float v = sel ? f.y : f.x;
                    if (q == 0) s0 += v; else if (q == 1) s1 += v;
                    else if (q == 2) s2 += v; else s3 += v;
                }
            }
            float iv = sigm(s0), fv = sigm(s1), gv = tanha(s2), ov = sigm(s3);
            c1_state = fv * c1_state + iv * gv;
            float h1val = ov * tanha(c1_state);
            unsigned hb = (unsigned)__half_as_ushort(__float2half_rn(h1val));
            unsigned ob = __shfl_xor_sync(0xffffffffu, hb, 1);
            if ((ej & 1) == 0)
                g_h1H[(r + 1) & 1][foff] = (hb & 0xffffu) | (ob << 16);
            // residual from hbuf hole, slot (r-1)&3
            {
                int d = (r - 1) & 3;
                const unsigned* hrow = (d < 2 ? RshA : RshB) + (d & 1) * 128 * RPK + hb_row;
                float h0_res = __half2float(((const __half*)hrow)[hb_sel]);
                outseq[((size_t)eb * T_ + (r - 1)) * H_ + hcol] = h1val + h0_res;
            }
            __syncwarp();
            if (lane == 0) flag_release_idx(g_f1, bid & 15);
        }
    }
}

// ---------------- launch ----------------
extern "C" void kernel_launch(void* const* d_in, const int* in_sizes, int n_in,
                              void* d_out, int out_size) {
    const float* x    = (const float*)d_in[0];
    const float* Wih0 = (const float*)d_in[1];
    const float* Whh0 = (const float*)d_in[2];
    const float* bih0 = (const float*)d_in[3];
    const float* bhh0 = (const float*)d_in[4];
    const float* Wih1 = (const float*)d_in[5];
    const float* Whh1 = (const float*)d_in[6];
    const float* bih1 = (const float*)d_in[7];
    const float* bhh1 = (const float*)d_in[8];
    float* out = (float*)d_out;

    cudaFuncSetAttribute(lstm_fused_kernel,
                         cudaFuncAttributeMaxDynamicSharedMemorySize, FUSED_SMEM);

    void* p;
    cudaGetSymbolAddress(&p, g_xg);  float* xg = (float*)p;
    cudaGetSymbolAddress(&p, g_f0);  unsigned* f0 = (unsigned*)p;
    cudaGetSymbolAddress(&p, g_f1);  unsigned* f1 = (unsigned*)p;

    dim3 gg(32, 128);

    cudaMemsetAsync(f0, 0, sizeof(unsigned) * NC0 * CSTR);
    cudaMemsetAsync(f1, 0, sizeof(unsigned) * NC1 * CSTR);
    gemm_xg_kernel<<<gg, 256>>>(x, Wih0, bih0, bhh0, xg);
    lstm_fused_kernel<<<NBLK, NTHR, FUSED_SMEM>>>(xg, Whh0, Wih1, Whh1, bih1, bhh1, out);
}